// round 5
// baseline (speedup 1.0000x reference)
#include <cuda_runtime.h>

// UniversalRNN: 2-layer tanh RNN (B=2048, T=512, IN=1, H=64) + FC(64->1).
// Fully fused persistent kernel: each CTA owns 16 batch rows for all 512
// steps of BOTH layers (layer1 step t only needs layer0 output at t), then
// applies the FC head. All weights + double-buffered hidden states live in
// dynamic shared memory. fp32 CUDA-core FFMA throughput bound.

constexpr int Bq = 2048;
constexpr int Tt = 512;
constexpr int BB = 16;    // batch rows per CTA
constexpr int NT = 256;   // threads per CTA
constexpr int HP = 68;    // padded row pitch (floats) -> conflict-free fl4 LDS
constexpr int XS = 65;    // x chunk row pitch

// tanh via ex2/rcp approx: tanh(x) = 1 - 2/(exp2(2x*log2(e)) + 1)
// ~1e-6 abs error (vs ~6e-4 for tanh.approx — too risky over 512 recurrent steps)
__device__ __forceinline__ float fast_tanhf(float x) {
    float e;
    asm("ex2.approx.f32 %0, %1;" : "=f"(e) : "f"(x * 2.8853900817779268f));
    float r;
    asm("rcp.approx.f32 %0, %1;" : "=f"(r) : "f"(e + 1.0f));
    return fmaf(-2.0f, r, 1.0f);
}

// function, NOT a macro: a macro parameter named `w` is captured by the
// member-access tokens `.w` during expansion. A function has proper scoping
// and identical codegen after inlining.
__device__ __forceinline__ void fma4(float& acc, const float4& a, const float4& b) {
    acc = fmaf(a.x, b.x, acc);
    acc = fmaf(a.y, b.y, acc);
    acc = fmaf(a.z, b.z, acc);
    acc = fmaf(a.w, b.w, acc);
}

__global__ __launch_bounds__(NT, 1) void rnn_fused_kernel(
    const float* __restrict__ x,      // [B, T, 1]
    const float* __restrict__ Wih0,   // [64, 1]
    const float* __restrict__ Whh0,   // [64, 64]
    const float* __restrict__ bih0,   // [64]
    const float* __restrict__ bhh0,   // [64]
    const float* __restrict__ Wih1,   // [64, 64]
    const float* __restrict__ Whh1,   // [64, 64]
    const float* __restrict__ bih1,   // [64]
    const float* __restrict__ bhh1,   // [64]
    const float* __restrict__ Wfc,    // [1, 64]
    const float* __restrict__ bfc,    // [1]
    float* __restrict__ out)          // [B, 1]
{
    extern __shared__ float sm[];
    float* W0  = sm;                 // Whh0 [64][HP]
    float* Wi1 = W0  + 64 * HP;      // Wih1 [64][HP]
    float* Wh1 = Wi1 + 64 * HP;      // Whh1 [64][HP]
    float* h0s = Wh1 + 64 * HP;      // [2][BB][HP] double-buffered
    float* h1s = h0s + 2 * BB * HP;  // [2][BB][HP]
    float* xs  = h1s + 2 * BB * HP;  // [BB][XS] x chunk (64 timesteps)
    float* wfc = xs  + BB * XS;      // [64]

    const int tx = threadIdx.x;
    const int b0 = blockIdx.x * BB;

    // ---- stage weights into shared (padded pitch) ----
    for (int idx = tx; idx < 64 * 64; idx += NT) {
        int r = idx >> 6, c = idx & 63;
        W0 [r * HP + c] = Whh0[idx];
        Wi1[r * HP + c] = Wih1[idx];
        Wh1[r * HP + c] = Whh1[idx];
    }
    if (tx < 64) wfc[tx] = Wfc[tx];
    for (int idx = tx; idx < 2 * BB * HP; idx += NT) {
        h0s[idx] = 0.0f;
        h1s[idx] = 0.0f;
    }

    // thread tile: batch rows {bp, bp+8}, output dims {2dq, 2dq+1}
    const int bp = tx & 7;
    const int dq = tx >> 3;
    const int r0 = bp, r1 = bp + 8;
    const int i0 = 2 * dq;

    const float wxa = Wih0[i0], wxb = Wih0[i0 + 1];
    const float b0a = bih0[i0] + bhh0[i0];
    const float b0b = bih0[i0 + 1] + bhh0[i0 + 1];
    const float b1a = bih1[i0] + bhh1[i0];
    const float b1b = bih1[i0 + 1] + bhh1[i0 + 1];

    __syncthreads();

    int cur = 0;
    for (int t = 0; t < Tt; ++t) {
        // refill x chunk every 64 steps (prior step's end-barrier orders this)
        if ((t & 63) == 0) {
            #pragma unroll
            for (int j = 0; j < (BB * 64) / NT; ++j) {
                int idx = tx + j * NT;
                int r = idx >> 6, c = idx & 63;
                xs[r * XS + c] = x[(b0 + r) * Tt + t + c];
            }
            __syncthreads();
        }
        const int tc = t & 63;
        const float* h0c = h0s + cur * BB * HP;
        float*       h0n = h0s + (cur ^ 1) * BB * HP;
        const float* h1c = h1s + cur * BB * HP;
        float*       h1n = h1s + (cur ^ 1) * BB * HP;

        // ---- phase 1: layer-0 step  h0' = tanh(x*wih0 + b + Whh0 h0) ----
        const float xv0 = xs[r0 * XS + tc];
        const float xv1 = xs[r1 * XS + tc];
        float a00 = fmaf(xv0, wxa, b0a);
        float a01 = fmaf(xv0, wxb, b0b);
        float a10 = fmaf(xv1, wxa, b0a);
        float a11 = fmaf(xv1, wxb, b0b);
        #pragma unroll
        for (int q = 0; q < 16; ++q) {
            float4 ha = *(const float4*)(h0c + r0 * HP + 4 * q);
            float4 hb = *(const float4*)(h0c + r1 * HP + 4 * q);
            float4 wa = *(const float4*)(W0 + i0 * HP + 4 * q);
            float4 wb = *(const float4*)(W0 + (i0 + 1) * HP + 4 * q);
            fma4(a00, ha, wa); fma4(a01, ha, wb);
            fma4(a10, hb, wa); fma4(a11, hb, wb);
        }
        {
            float2 v0 = make_float2(fast_tanhf(a00), fast_tanhf(a01));
            float2 v1 = make_float2(fast_tanhf(a10), fast_tanhf(a11));
            *(float2*)(h0n + r0 * HP + i0) = v0;
            *(float2*)(h0n + r1 * HP + i0) = v1;
        }
        __syncthreads();

        // ---- phase 2: layer-1 step  h1' = tanh(Wih1 h0' + b + Whh1 h1) ----
        a00 = b1a; a01 = b1b; a10 = b1a; a11 = b1b;
        #pragma unroll
        for (int q = 0; q < 16; ++q) {
            float4 ga = *(const float4*)(h0n + r0 * HP + 4 * q);
            float4 gb = *(const float4*)(h0n + r1 * HP + 4 * q);
            float4 wa = *(const float4*)(Wi1 + i0 * HP + 4 * q);
            float4 wb = *(const float4*)(Wi1 + (i0 + 1) * HP + 4 * q);
            fma4(a00, ga, wa); fma4(a01, ga, wb);
            fma4(a10, gb, wa); fma4(a11, gb, wb);
            float4 ha = *(const float4*)(h1c + r0 * HP + 4 * q);
            float4 hb = *(const float4*)(h1c + r1 * HP + 4 * q);
            float4 va = *(const float4*)(Wh1 + i0 * HP + 4 * q);
            float4 vb = *(const float4*)(Wh1 + (i0 + 1) * HP + 4 * q);
            fma4(a00, ha, va); fma4(a01, ha, vb);
            fma4(a10, hb, va); fma4(a11, hb, vb);
        }
        {
            float2 v0 = make_float2(fast_tanhf(a00), fast_tanhf(a01));
            float2 v1 = make_float2(fast_tanhf(a10), fast_tanhf(a11));
            *(float2*)(h1n + r0 * HP + i0) = v0;
            *(float2*)(h1n + r1 * HP + i0) = v1;
        }
        __syncthreads();
        cur ^= 1;
    }

    // ---- FC head: out[b] = Wfc . h1_last[b] + bfc ----
    const float* h1f = h1s + cur * BB * HP;
    if (tx < BB) {
        float acc = bfc[0];
        #pragma unroll
        for (int k = 0; k < 64; ++k)
            acc = fmaf(h1f[tx * HP + k], wfc[k], acc);
        out[b0 + tx] = acc;
    }
}

extern "C" void kernel_launch(void* const* d_in, const int* in_sizes, int n_in,
                              void* d_out, int out_size) {
    (void)in_sizes; (void)n_in; (void)out_size;
    const float* x    = (const float*)d_in[0];
    const float* Wih0 = (const float*)d_in[1];
    const float* Whh0 = (const float*)d_in[2];
    const float* bih0 = (const float*)d_in[3];
    const float* bhh0 = (const float*)d_in[4];
    const float* Wih1 = (const float*)d_in[5];
    const float* Whh1 = (const float*)d_in[6];
    const float* bih1 = (const float*)d_in[7];
    const float* bhh1 = (const float*)d_in[8];
    const float* Wfc  = (const float*)d_in[9];
    const float* bfc  = (const float*)d_in[10];
    float* out = (float*)d_out;

    constexpr int SMEM_FLOATS = 3 * 64 * HP + 4 * BB * HP + BB * XS + 64;
    constexpr int SMEM_BYTES  = SMEM_FLOATS * 4;  // 74048

    cudaFuncSetAttribute(rnn_fused_kernel,
                         cudaFuncAttributeMaxDynamicSharedMemorySize, SMEM_BYTES);

    dim3 grid(Bq / BB), block(NT);
    rnn_fused_kernel<<<grid, block, SMEM_BYTES>>>(
        x, Wih0, Whh0, bih0, bhh0, Wih1, Whh1, bih1, bhh1, Wfc, bfc, out);
}